// round 13
// baseline (speedup 1.0000x reference)
#include <cuda_runtime.h>
#include <cuda_bf16.h>
#include <cstdint>
#include <math.h>

#define NQ 4
#define NL 3
#define DIM 16

// W = [Re U; Im U] (32 rows x 16 cols), bf16 hi/lo split, row-major, packed
// as u32 bf16x2 pairs: g_Wh32[n*8 + c] = {W[n][2c], W[n][2c+1]}.
__device__ uint32_t g_Wh32[32 * 8];
__device__ uint32_t g_Wl32[32 * 8];

// ---------------------------------------------------------------------------
// Prekernel: 256 threads = 16 columns x 16 basis states, one complex
// amplitude per thread. Gates via shfl_xor butterflies (~500-cycle kernel).
// ---------------------------------------------------------------------------
__global__ void precompute_W_kernel(const float* __restrict__ params) {
    const int tid = threadIdx.x;          // 0..255
    const int j = tid >> 4;               // column (initial basis state)
    const int i = tid & 15;               // this thread's basis state index

    float re = (i == j) ? 1.0f : 0.0f;
    float im = 0.0f;

#pragma unroll
    for (int l = 0; l < NL; l++) {
#pragma unroll
        for (int w = 0; w < NQ; w++) {
            const int m = 1 << (3 - w);
            float ty = 0.5f * params[(l * NQ + w) * 2 + 0];
            float sy, cy;
            __sincosf(ty, &sy, &cy);
            float pre = __shfl_xor_sync(0xFFFFFFFFu, re, m);
            float pim = __shfl_xor_sync(0xFFFFFFFFu, im, m);
            if (i & m) {
                re = fmaf(cy, re,  sy * pre);
                im = fmaf(cy, im,  sy * pim);
            } else {
                re = fmaf(cy, re, -sy * pre);
                im = fmaf(cy, im, -sy * pim);
            }
            float tz = 0.5f * params[(l * NQ + w) * 2 + 1];
            float sz, cz;
            __sincosf(tz, &sz, &cz);
            float szs = (i & m) ? sz : -sz;
            float nre = fmaf(cz, re, -szs * im);
            float nim = fmaf(cz, im,  szs * re);
            re = nre;
            im = nim;
        }
#pragma unroll
        for (int w = 0; w < NQ - 1; w++) {
            const int mc = 1 << (3 - w);
            const int mt = 1 << (2 - w);
            float pre = __shfl_xor_sync(0xFFFFFFFFu, re, mt);
            float pim = __shfl_xor_sync(0xFFFFFFFFu, im, mt);
            if (i & mc) { re = pre; im = pim; }
        }
    }

    __nv_bfloat16* Wh = reinterpret_cast<__nv_bfloat16*>(g_Wh32);
    __nv_bfloat16* Wl = reinterpret_cast<__nv_bfloat16*>(g_Wl32);
    __nv_bfloat16 hr = __float2bfloat16(re);
    __nv_bfloat16 hi = __float2bfloat16(im);
    Wh[i * DIM + j]         = hr;
    Wh[(DIM + i) * DIM + j] = hi;
    Wl[i * DIM + j]         = __float2bfloat16(re - __bfloat162float(hr));
    Wl[(DIM + i) * DIM + j] = __float2bfloat16(im - __bfloat162float(hi));
}

// ---------------------------------------------------------------------------
// HMMA helpers (base-target sm_80+ instructions; no 'a' features)
// ---------------------------------------------------------------------------
__device__ __forceinline__ uint32_t smem_u32(const void* p) {
    uint32_t a;
    asm("{ .reg .u64 t; cvta.to.shared.u64 t, %1; cvt.u32.u64 %0, t; }"
        : "=r"(a) : "l"(p));
    return a;
}

__device__ __forceinline__ void ldmatrix_x4(uint32_t& r0, uint32_t& r1,
                                            uint32_t& r2, uint32_t& r3,
                                            uint32_t addr) {
    asm volatile("ldmatrix.sync.aligned.m8n8.x4.shared.b16 {%0,%1,%2,%3}, [%4];"
                 : "=r"(r0), "=r"(r1), "=r"(r2), "=r"(r3) : "r"(addr));
}

__device__ __forceinline__ void mma_bf16(float* d, uint32_t a0, uint32_t a1,
                                         uint32_t a2, uint32_t a3,
                                         uint32_t b0, uint32_t b1) {
    asm volatile(
        "mma.sync.aligned.m16n8k16.row.col.f32.bf16.bf16.f32 "
        "{%0,%1,%2,%3}, {%4,%5,%6,%7}, {%8,%9}, {%0,%1,%2,%3};"
        : "+f"(d[0]), "+f"(d[1]), "+f"(d[2]), "+f"(d[3])
        : "r"(a0), "r"(a1), "r"(a2), "r"(a3), "r"(b0), "r"(b1));
}

// hi/lo bf16 split of a float pair, packed {v0 -> lo half, v1 -> hi half}
__device__ __forceinline__ void split2(float v0, float v1,
                                       uint32_t& h, uint32_t& l) {
    asm("cvt.rn.bf16x2.f32 %0, %1, %2;" : "=r"(h) : "f"(v1), "f"(v0));
    float f0 = __uint_as_float(h << 16);
    float f1 = __uint_as_float(h & 0xFFFF0000u);
    float l0 = v0 - f0;
    float l1 = v1 - f1;
    asm("cvt.rn.bf16x2.f32 %0, %1, %2;" : "=r"(l) : "f"(l1), "f"(l0));
}

// ---------------------------------------------------------------------------
// Main kernel: 64 items/warp as two sequential 32-item groups reusing one
// 16KB staging buffer. W/sign fragments hoisted across all 4 tiles.
// __launch_bounds__(256, 5) caps regs at 48 -> 5 blocks/SM (40 warps).
// ---------------------------------------------------------------------------
__global__ __launch_bounds__(256, 5) void vqc_hmma_kernel(
    const float4* __restrict__ patch, float4* __restrict__ out, int n) {
    // per-warp staging: [8 warps][hi/lo][32 rows][8 u32]  (16 KB)
    __shared__ __align__(16) uint32_t stage[8][2][32][8];

    const int tid = threadIdx.x;
    const int wid = tid >> 5;
    const int lane = tid & 31;
    const int g = lane >> 2;      // 0..7
    const int t = lane & 3;       // 0..3

    const int itemBase = blockIdx.x * 512 + wid * 64;

    // ---- W (B) fragments, hoisted once for all 4 s-tiles ----
    uint32_t bh[4][2], bl[4][2];
#pragma unroll
    for (int nt = 0; nt < 4; nt++) {
        int idx = (nt * 8 + g) * 8 + t;
        bh[nt][0] = g_Wh32[idx];
        bh[nt][1] = g_Wh32[idx + 4];
        bl[nt][0] = g_Wl32[idx];
        bl[nt][1] = g_Wl32[idx + 4];
    }

    // ---- sign-matrix B fragment (Z[k=i][n=w], exact +-1 bf16), hoisted ----
    uint32_t bs0, bs1;
    {
        auto enc = [&](int i) -> uint32_t {
            if (g >= 4) return 0u;  // unused n columns
            return (((i >> (3 - g)) & 1) ? 0xBF80u : 0x3F80u);
        };
        bs0 = enc(2 * t) | (enc(2 * t + 1) << 16);
        bs1 = enc(2 * t + 8) | (enc(2 * t + 9) << 16);
    }

    float2* o2 = reinterpret_cast<float2*>(out);

#pragma unroll
    for (int u = 0; u < 2; u++) {
        // ---- load this group's patch and build s[16] hi/lo, stage row=lane --
        {
            int item = itemBase + u * 32 + lane;
            float4 p = patch[item < n ? item : (n - 1)];
            float s0, c0, s1, c1, s2, c2, s3, c3;
            __sincosf(0.5f * p.x, &s0, &c0);
            __sincosf(0.5f * p.y, &s1, &c1);
            __sincosf(0.5f * p.z, &s2, &c2);
            __sincosf(0.5f * p.w, &s3, &c3);
            float qa[4] = {c0 * c1, c0 * s1, s0 * c1, s0 * s1};
            float qb[4] = {c2 * c3, c2 * s3, s2 * c3, s2 * s3};

            uint32_t hi[8], lo[8];
#pragma unroll
            for (int c = 0; c < 8; c++) {
                int k0 = 2 * c, k1 = 2 * c + 1;
                float v0 = qa[k0 >> 2] * qb[k0 & 3];
                float v1 = qa[k1 >> 2] * qb[k1 & 3];
                split2(v0, v1, hi[c], lo[c]);
            }
            uint4* dh = reinterpret_cast<uint4*>(&stage[wid][0][lane][0]);
            uint4* dl = reinterpret_cast<uint4*>(&stage[wid][1][lane][0]);
            dh[0] = make_uint4(hi[0], hi[1], hi[2], hi[3]);
            dh[1] = make_uint4(hi[4], hi[5], hi[6], hi[7]);
            dl[0] = make_uint4(lo[0], lo[1], lo[2], lo[3]);
            dl[1] = make_uint4(lo[4], lo[5], lo[6], lo[7]);
        }
        __syncwarp();

#pragma unroll
        for (int sl = 0; sl < 2; sl++) {
            const int s = u * 2 + sl;     // global tile index (item block)
            uint32_t ah0, ah1, ah2, ah3, al0, al1, al2, al3;
            {
                int mrow = sl * 16 + (lane & 15);
                int chunk = (lane >> 4);
                uint32_t addrh = smem_u32(&stage[wid][0][mrow][chunk * 4]);
                uint32_t addrl = smem_u32(&stage[wid][1][mrow][chunk * 4]);
                ldmatrix_x4(ah0, ah1, ah2, ah3, addrh);
                ldmatrix_x4(al0, al1, al2, al3, addrl);
            }

            float acc[4][4];
#pragma unroll
            for (int nt = 0; nt < 4; nt++) {
                acc[nt][0] = acc[nt][1] = acc[nt][2] = acc[nt][3] = 0.0f;
                mma_bf16(acc[nt], ah0, ah1, ah2, ah3, bh[nt][0], bh[nt][1]);
                mma_bf16(acc[nt], ah0, ah1, ah2, ah3, bl[nt][0], bl[nt][1]);
                mma_bf16(acc[nt], al0, al1, al2, al3, bh[nt][0], bh[nt][1]);
            }

            // pr matrix P[16 items, 16 i] in exact A-fragment layout
            float prA = fmaf(acc[0][0], acc[0][0], acc[2][0] * acc[2][0]);
            float prB = fmaf(acc[0][1], acc[0][1], acc[2][1] * acc[2][1]);
            float prC = fmaf(acc[0][2], acc[0][2], acc[2][2] * acc[2][2]);
            float prD = fmaf(acc[0][3], acc[0][3], acc[2][3] * acc[2][3]);
            float prE = fmaf(acc[1][0], acc[1][0], acc[3][0] * acc[3][0]);
            float prF = fmaf(acc[1][1], acc[1][1], acc[3][1] * acc[3][1]);
            float prG = fmaf(acc[1][2], acc[1][2], acc[3][2] * acc[3][2]);
            float prH = fmaf(acc[1][3], acc[1][3], acc[3][3] * acc[3][3]);

            uint32_t ph0, pl0, ph1, pl1, ph2, pl2, ph3, pl3;
            split2(prA, prB, ph0, pl0);
            split2(prC, prD, ph1, pl1);
            split2(prE, prF, ph2, pl2);
            split2(prG, prH, ph3, pl3);

            float ev[4] = {0.0f, 0.0f, 0.0f, 0.0f};
            mma_bf16(ev, ph0, ph1, ph2, ph3, bs0, bs1);
            mma_bf16(ev, pl0, pl1, pl2, pl3, bs0, bs1);

            // ev frag: c0=(g, w=2t), c1=(g,2t+1), c2=(g+8,2t), c3=(g+8,2t+1)
            if (t < 2) {
                int it0 = itemBase + s * 16 + g;
                int it1 = it0 + 8;
                if (it0 < n) o2[it0 * 2 + t] = make_float2(ev[0], ev[1]);
                if (it1 < n) o2[it1 * 2 + t] = make_float2(ev[2], ev[3]);
            }
        }
        // ensure all lanes finished reading staging before group1 overwrites
        __syncwarp();
    }
}

// ---------------------------------------------------------------------------
extern "C" void kernel_launch(void* const* d_in, const int* in_sizes, int n_in,
                              void* d_out, int out_size) {
    const float* patch  = (const float*)d_in[0];   // (B, 4) float32
    const float* params = (const float*)d_in[1];   // (3, 4, 2) float32
    int n = in_sizes[0] / 4;                       // B

    precompute_W_kernel<<<1, 256>>>(params);

    int blocks = (n + 511) / 512;
    vqc_hmma_kernel<<<blocks, 256>>>(
        (const float4*)patch, (float4*)d_out, n);
}